// round 6
// baseline (speedup 1.0000x reference)
#include <cuda_runtime.h>
#include <math.h>

#define BB     8
#define NFULL  8192
#define NPART  2048
#define DLAT   512
#define EPSV   1e-12f

__device__ float g_pf[BB * NFULL];
__device__ float g_fp[BB * NFULL];
__device__ float g_part[BB * NPART];

constexpr int RBLKS = 120;
__device__ float g_partial[4 * RBLKS];

constexpr int THREADS = 128;
constexpr int Q       = 8;                // queries per thread
constexpr int QPB     = THREADS * Q;      // 1024
constexpr int CHUNK   = 1024;             // refs per task tile
constexpr int CH2     = CHUNK / 2;        // packed ref pairs (16KB smem)

typedef unsigned long long u64;

__device__ __forceinline__ u64 pack2(float lo, float hi) {
    u64 r; asm("mov.b64 %0, {%1, %2};" : "=l"(r) : "f"(lo), "f"(hi)); return r;
}
__device__ __forceinline__ void unpack2(u64 v, float& lo, float& hi) {
    asm("mov.b64 {%0, %1}, %2;" : "=f"(lo), "=f"(hi) : "l"(v));
}
__device__ __forceinline__ u64 ffma2(u64 a, u64 b, u64 c) {
    u64 d; asm("fma.rn.f32x2 %0, %1, %2, %3;" : "=l"(d) : "l"(a), "l"(b), "l"(c)); return d;
}

// ---------------------------------------------------------------------------
// Task geometry: 1152 uniform tasks (1024 queries x 1024 refs each).
// Grid = 576 blocks, each runs tasks {bid, bid+576} -> single resident wave.
// ---------------------------------------------------------------------------
constexpr int RCHUNKS   = NFULL / CHUNK;            // 8
constexpr int CHAM_QT   = NFULL / QPB;              // 8
constexpr int FID_QT    = NPART / QPB;              // 2
constexpr int CHAM_BLKS = CHAM_QT * RCHUNKS * BB;   // 512
constexpr int FID_BLKS  = FID_QT * RCHUNKS * BB;    // 128
constexpr int TOT_TASKS = 2 * CHAM_BLKS + FID_BLKS; // 1152
constexpr int GRID      = TOT_TASKS / 2;            // 576
constexpr int TPB       = 2;                        // tasks per block

__global__ __launch_bounds__(THREADS)
void fused_rowmin_kernel(const float* __restrict__ pred,
                         const float* __restrict__ full,
                         const float* __restrict__ partial,
                         float* __restrict__ pf,
                         float* __restrict__ fp,
                         float* __restrict__ pp) {
    __shared__ ulonglong2 tA[CH2];   // (pack(x0,x1), pack(y0,y1))
    __shared__ ulonglong2 tB[CH2];   // (pack(z0,z1), pack(w0,w1))

    for (int t = 0; t < TPB; t++) {
        int l = blockIdx.x + t * GRID;

        // ---- decode task ----
        const float *q, *r;
        float* outmin;
        int Nq, qtiles;
        if (l < CHAM_BLKS) {
            q = pred; r = full; outmin = pf; Nq = NFULL; qtiles = CHAM_QT;
        } else if (l < 2 * CHAM_BLKS) {
            l -= CHAM_BLKS;
            q = full; r = pred; outmin = fp; Nq = NFULL; qtiles = CHAM_QT;
        } else {
            l -= 2 * CHAM_BLKS;
            q = partial; r = pred; outmin = pp; Nq = NPART; qtiles = FID_QT;
        }
        const int b  = l / (qtiles * RCHUNKS);
        const int rm = l % (qtiles * RCHUNKS);
        const int ck = rm / qtiles;
        const int qt = rm % qtiles;
        const int qbase = qt * QPB;
        const int rbase = ck * CHUNK;

        const float* qb = q + (size_t)b * Nq * 3;
        const float* rb = r + (size_t)b * NFULL * 3;

        __syncthreads();   // previous task's readers done before overwrite
        for (int j = threadIdx.x; j < CH2; j += THREADS) {
            int rj = rbase + 2 * j;
            float x0 = rb[rj * 3 + 0], y0 = rb[rj * 3 + 1], z0 = rb[rj * 3 + 2];
            float x1 = rb[rj * 3 + 3], y1 = rb[rj * 3 + 4], z1 = rb[rj * 3 + 5];
            float w0 = 0.5f * (x0 * x0 + y0 * y0 + z0 * z0);
            float w1 = 0.5f * (x1 * x1 + y1 * y1 + z1 * z1);
            ulonglong2 a, bb;
            a.x  = pack2(x0, x1); a.y  = pack2(y0, y1);
            bb.x = pack2(z0, z1); bb.y = pack2(w0, w1);
            tA[j] = a;
            tB[j] = bb;
        }
        __syncthreads();

        // ---- per-thread queries (negated, broadcast-packed) ----
        u64 nqx[Q], nqy[Q], nqz[Q];
        float q2[Q], m0[Q], m1[Q];
#pragma unroll
        for (int k = 0; k < Q; k++) {
            int qi = qbase + threadIdx.x + k * THREADS;
            float x = qb[qi * 3 + 0];
            float y = qb[qi * 3 + 1];
            float z = qb[qi * 3 + 2];
            nqx[k] = pack2(-x, -x);
            nqy[k] = pack2(-y, -y);
            nqz[k] = pack2(-z, -z);
            q2[k]  = x * x + y * y + z * z;
            m0[k]  = __int_as_float(0x7f800000);
            m1[k]  = __int_as_float(0x7f800000);
        }

        // ---- main loop: 2 refs x 8 queries per iter ----
#pragma unroll 2
        for (int j = 0; j < CH2; j++) {
            ulonglong2 A = tA[j];
            ulonglong2 B = tB[j];
#pragma unroll
            for (int k = 0; k < Q; k++) {
                u64 v = ffma2(nqz[k], B.x, B.y);
                v = ffma2(nqy[k], A.y, v);
                v = ffma2(nqx[k], A.x, v);
                float v0, v1;
                unpack2(v, v0, v1);
                m0[k] = fminf(m0[k], v0);
                m1[k] = fminf(m1[k], v1);
            }
        }

        // ---- writeback ----
#pragma unroll
        for (int k = 0; k < Q; k++) {
            int qi   = qbase + threadIdx.x + k * THREADS;
            float mn = fminf(m0[k], m1[k]);
            float sq = fmaf(2.0f, mn, q2[k]);
            float v  = fmaxf(sq, EPSV);
            atomicMin((unsigned int*)&outmin[(size_t)b * Nq + qi], __float_as_uint(v));
        }
    }
}

// ---------------------------------------------------------------------------
__global__ __launch_bounds__(256)
void reduce1_kernel(const float* __restrict__ pf,
                    const float* __restrict__ fp,
                    const float* __restrict__ pp,
                    const float* __restrict__ mu,
                    const float* __restrict__ lv,
                    float* __restrict__ partials) {
    const int tid    = threadIdx.x;
    const int stride = gridDim.x * blockDim.x;
    const int g      = blockIdx.x * blockDim.x + tid;

    float s_pf = 0.f, s_fp = 0.f, s_pp = 0.f, s_kl = 0.f;
    for (int i = g; i < BB * NFULL; i += stride) {
        s_pf += sqrtf(pf[i]);
        s_fp += sqrtf(fp[i]);
    }
    for (int i = g; i < BB * NPART; i += stride) s_pp += sqrtf(pp[i]);
    for (int i = g; i < BB * DLAT; i += stride) {
        float m = mu[i], l = lv[i];
        s_kl += 1.0f + l - m * m - expf(l);
    }

    __shared__ float sh[4][8];
#pragma unroll
    for (int off = 16; off > 0; off >>= 1) {
        s_pf += __shfl_down_sync(0xffffffffu, s_pf, off);
        s_fp += __shfl_down_sync(0xffffffffu, s_fp, off);
        s_pp += __shfl_down_sync(0xffffffffu, s_pp, off);
        s_kl += __shfl_down_sync(0xffffffffu, s_kl, off);
    }
    int wid = tid >> 5, lid = tid & 31;
    if (lid == 0) { sh[0][wid] = s_pf; sh[1][wid] = s_fp; sh[2][wid] = s_pp; sh[3][wid] = s_kl; }
    __syncthreads();

    if (tid < 4) {
        float acc = 0.f;
#pragma unroll
        for (int w = 0; w < 8; w++) acc += sh[tid][w];
        partials[tid * RBLKS + blockIdx.x] = acc;
    }
}

// ---------------------------------------------------------------------------
__global__ __launch_bounds__(128)
void reduce2_kernel(const float* __restrict__ partials,
                    float* __restrict__ out) {
    const int tid = threadIdx.x;
    const int wid = tid >> 5;
    const int lid = tid & 31;

    float s = 0.f;
    for (int i = lid; i < RBLKS; i += 32) s += partials[wid * RBLKS + i];
#pragma unroll
    for (int off = 16; off > 0; off >>= 1)
        s += __shfl_down_sync(0xffffffffu, s, off);

    __shared__ float sums[4];
    if (lid == 0) sums[wid] = s;
    __syncthreads();

    if (tid == 0) {
        float inv_nf = 1.0f / (float)(BB * NFULL);
        float cd  = 0.5f * (sums[0] + sums[1]) * inv_nf;
        float fid = sums[2] / (float)(BB * NPART);
        float kl  = -0.5f * sums[3] / (float)BB;
        float total = 1.0f * cd + 0.01f * kl + 0.5f * fid;
        out[0] = total;
        out[1] = cd;
        out[2] = kl;
        out[3] = fid;
    }
}

// ---------------------------------------------------------------------------
extern "C" void kernel_launch(void* const* d_in, const int* in_sizes, int n_in,
                              void* d_out, int out_size) {
    const float* pred    = (const float*)d_in[0];
    const float* full    = (const float*)d_in[1];
    const float* partial = (const float*)d_in[2];
    const float* mu      = (const float*)d_in[3];
    const float* logvar  = (const float*)d_in[4];
    float* out = (float*)d_out;

    float *pf, *fp, *pp, *pt;
    cudaGetSymbolAddress((void**)&pf, g_pf);
    cudaGetSymbolAddress((void**)&fp, g_fp);
    cudaGetSymbolAddress((void**)&pp, g_part);
    cudaGetSymbolAddress((void**)&pt, g_partial);

    cudaMemsetAsync(pf, 0x7f, BB * NFULL * sizeof(float));
    cudaMemsetAsync(fp, 0x7f, BB * NFULL * sizeof(float));
    cudaMemsetAsync(pp, 0x7f, BB * NPART * sizeof(float));

    fused_rowmin_kernel<<<GRID, THREADS>>>(pred, full, partial, pf, fp, pp);

    reduce1_kernel<<<RBLKS, 256>>>(pf, fp, pp, mu, logvar, pt);
    reduce2_kernel<<<1, 128>>>(pt, out);
}

// round 8
// speedup vs baseline: 1.1042x; 1.1042x over previous
#include <cuda_runtime.h>
#include <math.h>

#define BB     8
#define NFULL  8192
#define NPART  2048
#define DLAT   512
#define EPSV   1e-12f

__device__ float g_pf[BB * NFULL];
__device__ float g_fp[BB * NFULL];
__device__ float g_part[BB * NPART];

constexpr int RBLKS = 120;
__device__ float g_partial[4 * RBLKS];

constexpr int THREADS = 128;              // 4 warps
constexpr int WARPS   = 4;
constexpr int Q       = 8;                // queries per thread (4 packed pairs)
constexpr int QP      = Q / 2;
constexpr int QPB     = THREADS * Q;      // 1024 queries per task
constexpr int CHUNK   = 512;              // refs per task

typedef unsigned long long u64;

__device__ __forceinline__ u64 pack2(float lo, float hi) {
    u64 r; asm("mov.b64 %0, {%1, %2};" : "=l"(r) : "f"(lo), "f"(hi)); return r;
}
__device__ __forceinline__ void unpack2(u64 v, float& lo, float& hi) {
    asm("mov.b64 {%0, %1}, %2;" : "=f"(lo), "=f"(hi) : "l"(v));
}
__device__ __forceinline__ u64 ffma2(u64 a, u64 b, u64 c) {
    u64 d; asm("fma.rn.f32x2 %0, %1, %2, %3;" : "=l"(d) : "l"(a), "l"(b), "l"(c)); return d;
}
__device__ __forceinline__ u64 fadd2(u64 a, u64 b) {
    u64 d; asm("add.rn.f32x2 %0, %1, %2;" : "=l"(d) : "l"(a), "l"(b)); return d;
}
// Warp-min of a NON-NEGATIVE float via integer redux (bit order == float order).
__device__ __forceinline__ float warp_min_pos(float v) {
    unsigned int r;
    asm("redux.sync.min.u32 %0, %1, 0xffffffff;"
        : "=r"(r) : "r"(__float_as_uint(v)));
    return __uint_as_float(r);
}

// ---------------------------------------------------------------------------
// Symmetric chamfer: tile (1024 pred-queries x 512 full-refs) computed once;
// row mins -> pf, col mins -> fp.  Fidelity tasks: rows only -> pp.
// s_ij = u_i + w_j - dot_ij = |q-r|^2 / 2  (>= 0)
// ---------------------------------------------------------------------------
constexpr int RCK       = NFULL / CHUNK;             // 16
constexpr int CHAM_QT   = NFULL / QPB;               // 8
constexpr int FID_QT    = NPART / QPB;               // 2
constexpr int SYM_TASKS = CHAM_QT * RCK * BB;        // 1024
constexpr int FID_TASKS = FID_QT * RCK * BB;         // 256
constexpr int GRID      = SYM_TASKS + FID_TASKS;     // 1280

__global__ __launch_bounds__(THREADS)
void fused_rowmin_kernel(const float* __restrict__ pred,
                         const float* __restrict__ full,
                         const float* __restrict__ partial,
                         float* __restrict__ pf,
                         float* __restrict__ fp,
                         float* __restrict__ pp) {
    __shared__ ulonglong2 tA[CHUNK];            // (pack(x,x), pack(y,y))  8KB
    __shared__ ulonglong2 tB[CHUNK];            // (pack(z,z), pack(w,w))  8KB
    __shared__ float      colmin[WARPS][CHUNK]; // 8KB

    const int tid = threadIdx.x;
    const int wid = tid >> 5;
    const int lid = tid & 31;

    // ---- decode task ----
    const float *q, *r;
    float *rowout;
    bool sym;
    int b, ck, qt, Nq;
    int l = blockIdx.x;
    if (l < SYM_TASKS) {
        sym = true;
        b  = l >> 7;
        int rm = l & 127;
        ck = rm >> 3;
        qt = rm & 7;
        q = pred; r = full; rowout = pf; Nq = NFULL;
    } else {
        sym = false;
        l -= SYM_TASKS;
        b  = l >> 5;
        int rm = l & 31;
        ck = rm >> 1;
        qt = rm & 1;
        q = partial; r = pred; rowout = pp; Nq = NPART;
    }
    const int qbase = qt * QPB;
    const int rbase = ck * CHUNK;

    const float* qb = q + (size_t)b * Nq * 3;
    const float* rb = r + (size_t)b * NFULL * 3;

    // ---- tile load: dup-packed refs ----
    for (int j = tid; j < CHUNK; j += THREADS) {
        int rj = rbase + j;
        float x = rb[rj * 3 + 0];
        float y = rb[rj * 3 + 1];
        float z = rb[rj * 3 + 2];
        float w = 0.5f * (x * x + y * y + z * z);
        ulonglong2 a, bb;
        a.x  = pack2(x, x); a.y  = pack2(y, y);
        bb.x = pack2(z, z); bb.y = pack2(w, w);
        tA[j] = a;
        tB[j] = bb;
    }
    __syncthreads();

    // ---- per-thread queries: 4 packed pairs, negated coords + u = |q|^2/2 ----
    u64 nqx[QP], nqy[QP], nqz[QP], up[QP];
    float m0[QP], m1[QP];
    const float* qrow = qb + (size_t)(qbase + tid * Q) * 3;
#pragma unroll
    for (int k = 0; k < QP; k++) {
        float x0 = qrow[6 * k + 0], y0 = qrow[6 * k + 1], z0 = qrow[6 * k + 2];
        float x1 = qrow[6 * k + 3], y1 = qrow[6 * k + 4], z1 = qrow[6 * k + 5];
        nqx[k] = pack2(-x0, -x1);
        nqy[k] = pack2(-y0, -y1);
        nqz[k] = pack2(-z0, -z1);
        up[k]  = pack2(0.5f * (x0 * x0 + y0 * y0 + z0 * z0),
                       0.5f * (x1 * x1 + y1 * y1 + z1 * z1));
        m0[k]  = __int_as_float(0x7f800000);
        m1[k]  = __int_as_float(0x7f800000);
    }

    // ---- main loop: 1 ref x 8 queries per iter; s = (u + w) - dot >= 0 ----
    if (sym) {
#pragma unroll 2
        for (int j = 0; j < CHUNK; j++) {
            ulonglong2 A = tA[j];
            ulonglong2 B = tB[j];
            float c = __int_as_float(0x7f800000);
#pragma unroll
            for (int k = 0; k < QP; k++) {
                u64 s = ffma2(nqz[k], B.x, fadd2(B.y, up[k]));
                s = ffma2(nqy[k], A.y, s);
                s = ffma2(nqx[k], A.x, s);
                float s0, s1;
                unpack2(s, s0, s1);
                m0[k] = fminf(m0[k], s0);
                m1[k] = fminf(m1[k], s1);
                c = fminf(c, fminf(s0, s1));
            }
            float cw = warp_min_pos(c);
            if (lid == 0) colmin[wid][j] = cw;
        }
    } else {
#pragma unroll 2
        for (int j = 0; j < CHUNK; j++) {
            ulonglong2 A = tA[j];
            ulonglong2 B = tB[j];
#pragma unroll
            for (int k = 0; k < QP; k++) {
                u64 s = ffma2(nqz[k], B.x, fadd2(B.y, up[k]));
                s = ffma2(nqy[k], A.y, s);
                s = ffma2(nqx[k], A.x, s);
                float s0, s1;
                unpack2(s, s0, s1);
                m0[k] = fminf(m0[k], s0);
                m1[k] = fminf(m1[k], s1);
            }
        }
    }

    // ---- row writeback: sq = 2 * s_min ----
#pragma unroll
    for (int k = 0; k < QP; k++) {
        int qi = qbase + tid * Q + 2 * k;
        float s0 = fmaxf(m0[k] + m0[k], EPSV);
        float s1 = fmaxf(m1[k] + m1[k], EPSV);
        atomicMin((unsigned int*)&rowout[(size_t)b * Nq + qi],     __float_as_uint(s0));
        atomicMin((unsigned int*)&rowout[(size_t)b * Nq + qi + 1], __float_as_uint(s1));
    }

    // ---- col writeback (chamfer only): merge 4 warps ----
    if (sym) {
        __syncthreads();
        for (int j = tid; j < CHUNK; j += THREADS) {
            float v = fminf(fminf(colmin[0][j], colmin[1][j]),
                            fminf(colmin[2][j], colmin[3][j]));
            float sq = fmaxf(v + v, EPSV);
            atomicMin((unsigned int*)&fp[(size_t)b * NFULL + rbase + j],
                      __float_as_uint(sq));
        }
    }
}

// ---------------------------------------------------------------------------
__global__ __launch_bounds__(256)
void reduce1_kernel(const float* __restrict__ pf,
                    const float* __restrict__ fp,
                    const float* __restrict__ pp,
                    const float* __restrict__ mu,
                    const float* __restrict__ lv,
                    float* __restrict__ partials) {
    const int tid    = threadIdx.x;
    const int stride = gridDim.x * blockDim.x;
    const int g      = blockIdx.x * blockDim.x + tid;

    float s_pf = 0.f, s_fp = 0.f, s_pp = 0.f, s_kl = 0.f;
    for (int i = g; i < BB * NFULL; i += stride) {
        s_pf += sqrtf(pf[i]);
        s_fp += sqrtf(fp[i]);
    }
    for (int i = g; i < BB * NPART; i += stride) s_pp += sqrtf(pp[i]);
    for (int i = g; i < BB * DLAT; i += stride) {
        float m = mu[i], l = lv[i];
        s_kl += 1.0f + l - m * m - expf(l);
    }

    __shared__ float sh[4][8];
#pragma unroll
    for (int off = 16; off > 0; off >>= 1) {
        s_pf += __shfl_down_sync(0xffffffffu, s_pf, off);
        s_fp += __shfl_down_sync(0xffffffffu, s_fp, off);
        s_pp += __shfl_down_sync(0xffffffffu, s_pp, off);
        s_kl += __shfl_down_sync(0xffffffffu, s_kl, off);
    }
    int wid = tid >> 5, lid = tid & 31;
    if (lid == 0) { sh[0][wid] = s_pf; sh[1][wid] = s_fp; sh[2][wid] = s_pp; sh[3][wid] = s_kl; }
    __syncthreads();

    if (tid < 4) {
        float acc = 0.f;
#pragma unroll
        for (int w = 0; w < 8; w++) acc += sh[tid][w];
        partials[tid * RBLKS + blockIdx.x] = acc;
    }
}

// ---------------------------------------------------------------------------
__global__ __launch_bounds__(128)
void reduce2_kernel(const float* __restrict__ partials,
                    float* __restrict__ out) {
    const int tid = threadIdx.x;
    const int wid = tid >> 5;
    const int lid = tid & 31;

    float s = 0.f;
    for (int i = lid; i < RBLKS; i += 32) s += partials[wid * RBLKS + i];
#pragma unroll
    for (int off = 16; off > 0; off >>= 1)
        s += __shfl_down_sync(0xffffffffu, s, off);

    __shared__ float sums[4];
    if (lid == 0) sums[wid] = s;
    __syncthreads();

    if (tid == 0) {
        float inv_nf = 1.0f / (float)(BB * NFULL);
        float cd  = 0.5f * (sums[0] + sums[1]) * inv_nf;
        float fid = sums[2] / (float)(BB * NPART);
        float kl  = -0.5f * sums[3] / (float)BB;
        float total = 1.0f * cd + 0.01f * kl + 0.5f * fid;
        out[0] = total;
        out[1] = cd;
        out[2] = kl;
        out[3] = fid;
    }
}

// ---------------------------------------------------------------------------
extern "C" void kernel_launch(void* const* d_in, const int* in_sizes, int n_in,
                              void* d_out, int out_size) {
    const float* pred    = (const float*)d_in[0];
    const float* full    = (const float*)d_in[1];
    const float* partial = (const float*)d_in[2];
    const float* mu      = (const float*)d_in[3];
    const float* logvar  = (const float*)d_in[4];
    float* out = (float*)d_out;

    float *pf, *fp, *pp, *pt;
    cudaGetSymbolAddress((void**)&pf, g_pf);
    cudaGetSymbolAddress((void**)&fp, g_fp);
    cudaGetSymbolAddress((void**)&pp, g_part);
    cudaGetSymbolAddress((void**)&pt, g_partial);

    cudaMemsetAsync(pf, 0x7f, BB * NFULL * sizeof(float));
    cudaMemsetAsync(fp, 0x7f, BB * NFULL * sizeof(float));
    cudaMemsetAsync(pp, 0x7f, BB * NPART * sizeof(float));

    fused_rowmin_kernel<<<GRID, THREADS>>>(pred, full, partial, pf, fp, pp);

    reduce1_kernel<<<RBLKS, 256>>>(pf, fp, pp, mu, logvar, pt);
    reduce2_kernel<<<1, 128>>>(pt, out);
}

// round 9
// speedup vs baseline: 1.1897x; 1.0775x over previous
#include <cuda_runtime.h>
#include <math.h>

#define BB     8
#define NFULL  8192
#define NPART  2048
#define DLAT   512
#define EPSV   1e-12f

__device__ float g_pf[BB * NFULL];
__device__ float g_fp[BB * NFULL];
__device__ float g_part[BB * NPART];

constexpr int RBLKS = 120;
__device__ float g_partial[4 * RBLKS];

constexpr int THREADS = 128;              // 4 warps
constexpr int WARPS   = 4;
constexpr int Q       = 8;                // queries per thread (4 packed pairs)
constexpr int QP      = Q / 2;
constexpr int QPB     = THREADS * Q;      // 1024 queries per task
constexpr int CHUNK   = 512;              // refs per task

typedef unsigned long long u64;

__device__ __forceinline__ u64 pack2(float lo, float hi) {
    u64 r; asm("mov.b64 %0, {%1, %2};" : "=l"(r) : "f"(lo), "f"(hi)); return r;
}
__device__ __forceinline__ void unpack2(u64 v, float& lo, float& hi) {
    asm("mov.b64 {%0, %1}, %2;" : "=f"(lo), "=f"(hi) : "l"(v));
}
__device__ __forceinline__ u64 ffma2(u64 a, u64 b, u64 c) {
    u64 d; asm("fma.rn.f32x2 %0, %1, %2, %3;" : "=l"(d) : "l"(a), "l"(b), "l"(c)); return d;
}
__device__ __forceinline__ u64 fadd2(u64 a, u64 b) {
    u64 d; asm("add.rn.f32x2 %0, %1, %2;" : "=l"(d) : "l"(a), "l"(b)); return d;
}
// Warp-min of a NON-NEGATIVE float via integer redux (bit order == float order).
__device__ __forceinline__ float warp_min_pos(float v) {
    unsigned int r;
    asm("redux.sync.min.u32 %0, %1, 0xffffffff;"
        : "=r"(r) : "r"(__float_as_uint(v)));
    return __uint_as_float(r);
}

// ---------------------------------------------------------------------------
// Symmetric chamfer: tile (1024 pred-queries x 512 full-refs) computed once;
// row mins -> pf, col mins -> fp.  Fidelity tasks: rows only -> pp.
// s_ij = u_i + w_j - dot_ij = |q-r|^2 / 2  (>= 0)
// ---------------------------------------------------------------------------
constexpr int RCK       = NFULL / CHUNK;             // 16
constexpr int CHAM_QT   = NFULL / QPB;               // 8
constexpr int FID_QT    = NPART / QPB;               // 2
constexpr int SYM_TASKS = CHAM_QT * RCK * BB;        // 1024
constexpr int FID_TASKS = FID_QT * RCK * BB;         // 256
constexpr int GRID      = SYM_TASKS + FID_TASKS;     // 1280

__global__ __launch_bounds__(THREADS)
void fused_rowmin_kernel(const float* __restrict__ pred,
                         const float* __restrict__ full,
                         const float* __restrict__ partial,
                         float* __restrict__ pf,
                         float* __restrict__ fp,
                         float* __restrict__ pp) {
    __shared__ ulonglong2 tA[CHUNK];            // (pack(x,x), pack(y,y))  8KB
    __shared__ ulonglong2 tB[CHUNK];            // (pack(z,z), pack(w,w))  8KB
    __shared__ float      colmin[WARPS][CHUNK]; // 8KB

    const int tid = threadIdx.x;
    const int wid = tid >> 5;
    const int lid = tid & 31;

    // ---- decode task ----
    const float *q, *r;
    float *rowout;
    bool sym;
    int b, ck, qt, Nq;
    int l = blockIdx.x;
    if (l < SYM_TASKS) {
        sym = true;
        b  = l >> 7;
        int rm = l & 127;
        ck = rm >> 3;
        qt = rm & 7;
        q = pred; r = full; rowout = pf; Nq = NFULL;
    } else {
        sym = false;
        l -= SYM_TASKS;
        b  = l >> 5;
        int rm = l & 31;
        ck = rm >> 1;
        qt = rm & 1;
        q = partial; r = pred; rowout = pp; Nq = NPART;
    }
    const int qbase = qt * QPB;
    const int rbase = ck * CHUNK;

    const float* qb = q + (size_t)b * Nq * 3;
    const float* rb = r + (size_t)b * NFULL * 3;

    // ---- tile load: dup-packed refs ----
    for (int j = tid; j < CHUNK; j += THREADS) {
        int rj = rbase + j;
        float x = rb[rj * 3 + 0];
        float y = rb[rj * 3 + 1];
        float z = rb[rj * 3 + 2];
        float w = 0.5f * (x * x + y * y + z * z);
        ulonglong2 a, bb;
        a.x  = pack2(x, x); a.y  = pack2(y, y);
        bb.x = pack2(z, z); bb.y = pack2(w, w);
        tA[j] = a;
        tB[j] = bb;
    }
    __syncthreads();

    // ---- per-thread queries: 4 packed pairs, negated coords + u = |q|^2/2 ----
    u64 nqx[QP], nqy[QP], nqz[QP], up[QP];
    float m0[QP], m1[QP];
    const float* qrow = qb + (size_t)(qbase + tid * Q) * 3;
#pragma unroll
    for (int k = 0; k < QP; k++) {
        float x0 = qrow[6 * k + 0], y0 = qrow[6 * k + 1], z0 = qrow[6 * k + 2];
        float x1 = qrow[6 * k + 3], y1 = qrow[6 * k + 4], z1 = qrow[6 * k + 5];
        nqx[k] = pack2(-x0, -x1);
        nqy[k] = pack2(-y0, -y1);
        nqz[k] = pack2(-z0, -z1);
        up[k]  = pack2(0.5f * (x0 * x0 + y0 * y0 + z0 * z0),
                       0.5f * (x1 * x1 + y1 * y1 + z1 * z1));
        m0[k]  = __int_as_float(0x7f800000);
        m1[k]  = __int_as_float(0x7f800000);
    }

    // ---- main loop, software pipelined: prefetch j+1 while computing j ----
    if (sym) {
        ulonglong2 A = tA[0], B = tB[0];
#pragma unroll 4
        for (int j = 0; j < CHUNK; j++) {
            ulonglong2 An, Bn;
            if (j + 1 < CHUNK) { An = tA[j + 1]; Bn = tB[j + 1]; }
            u64 s[QP];
#pragma unroll
            for (int k = 0; k < QP; k++) {
                u64 t = ffma2(nqz[k], B.x, fadd2(B.y, up[k]));
                t = ffma2(nqy[k], A.y, t);
                s[k] = ffma2(nqx[k], A.x, t);
            }
            // row mins (8 independent accumulator chains) + balanced col tree
            float s0[QP], s1[QP];
#pragma unroll
            for (int k = 0; k < QP; k++) {
                unpack2(s[k], s0[k], s1[k]);
                m0[k] = fminf(m0[k], s0[k]);
                m1[k] = fminf(m1[k], s1[k]);
            }
            float ca = fminf(fminf(s0[0], s0[1]), fminf(s0[2], s0[3]));
            float cb = fminf(fminf(s1[0], s1[1]), fminf(s1[2], s1[3]));
            float cw = warp_min_pos(fminf(ca, cb));
            if (lid == 0) colmin[wid][j] = cw;
            A = An; B = Bn;
        }
    } else {
        ulonglong2 A = tA[0], B = tB[0];
#pragma unroll 4
        for (int j = 0; j < CHUNK; j++) {
            ulonglong2 An, Bn;
            if (j + 1 < CHUNK) { An = tA[j + 1]; Bn = tB[j + 1]; }
#pragma unroll
            for (int k = 0; k < QP; k++) {
                u64 t = ffma2(nqz[k], B.x, fadd2(B.y, up[k]));
                t = ffma2(nqy[k], A.y, t);
                t = ffma2(nqx[k], A.x, t);
                float s0, s1;
                unpack2(t, s0, s1);
                m0[k] = fminf(m0[k], s0);
                m1[k] = fminf(m1[k], s1);
            }
            A = An; B = Bn;
        }
    }

    // ---- row writeback: sq = 2 * s_min ----
#pragma unroll
    for (int k = 0; k < QP; k++) {
        int qi = qbase + tid * Q + 2 * k;
        float s0 = fmaxf(m0[k] + m0[k], EPSV);
        float s1 = fmaxf(m1[k] + m1[k], EPSV);
        atomicMin((unsigned int*)&rowout[(size_t)b * Nq + qi],     __float_as_uint(s0));
        atomicMin((unsigned int*)&rowout[(size_t)b * Nq + qi + 1], __float_as_uint(s1));
    }

    // ---- col writeback (chamfer only): merge 4 warps ----
    if (sym) {
        __syncthreads();
        for (int j = tid; j < CHUNK; j += THREADS) {
            float v = fminf(fminf(colmin[0][j], colmin[1][j]),
                            fminf(colmin[2][j], colmin[3][j]));
            float sq = fmaxf(v + v, EPSV);
            atomicMin((unsigned int*)&fp[(size_t)b * NFULL + rbase + j],
                      __float_as_uint(sq));
        }
    }
}

// ---------------------------------------------------------------------------
__global__ __launch_bounds__(256)
void reduce1_kernel(const float* __restrict__ pf,
                    const float* __restrict__ fp,
                    const float* __restrict__ pp,
                    const float* __restrict__ mu,
                    const float* __restrict__ lv,
                    float* __restrict__ partials) {
    const int tid    = threadIdx.x;
    const int stride = gridDim.x * blockDim.x;
    const int g      = blockIdx.x * blockDim.x + tid;

    float s_pf = 0.f, s_fp = 0.f, s_pp = 0.f, s_kl = 0.f;
    for (int i = g; i < BB * NFULL; i += stride) {
        s_pf += sqrtf(pf[i]);
        s_fp += sqrtf(fp[i]);
    }
    for (int i = g; i < BB * NPART; i += stride) s_pp += sqrtf(pp[i]);
    for (int i = g; i < BB * DLAT; i += stride) {
        float m = mu[i], l = lv[i];
        s_kl += 1.0f + l - m * m - expf(l);
    }

    __shared__ float sh[4][8];
#pragma unroll
    for (int off = 16; off > 0; off >>= 1) {
        s_pf += __shfl_down_sync(0xffffffffu, s_pf, off);
        s_fp += __shfl_down_sync(0xffffffffu, s_fp, off);
        s_pp += __shfl_down_sync(0xffffffffu, s_pp, off);
        s_kl += __shfl_down_sync(0xffffffffu, s_kl, off);
    }
    int wid = tid >> 5, lid = tid & 31;
    if (lid == 0) { sh[0][wid] = s_pf; sh[1][wid] = s_fp; sh[2][wid] = s_pp; sh[3][wid] = s_kl; }
    __syncthreads();

    if (tid < 4) {
        float acc = 0.f;
#pragma unroll
        for (int w = 0; w < 8; w++) acc += sh[tid][w];
        partials[tid * RBLKS + blockIdx.x] = acc;
    }
}

// ---------------------------------------------------------------------------
__global__ __launch_bounds__(128)
void reduce2_kernel(const float* __restrict__ partials,
                    float* __restrict__ out) {
    const int tid = threadIdx.x;
    const int wid = tid >> 5;
    const int lid = tid & 31;

    float s = 0.f;
    for (int i = lid; i < RBLKS; i += 32) s += partials[wid * RBLKS + i];
#pragma unroll
    for (int off = 16; off > 0; off >>= 1)
        s += __shfl_down_sync(0xffffffffu, s, off);

    __shared__ float sums[4];
    if (lid == 0) sums[wid] = s;
    __syncthreads();

    if (tid == 0) {
        float inv_nf = 1.0f / (float)(BB * NFULL);
        float cd  = 0.5f * (sums[0] + sums[1]) * inv_nf;
        float fid = sums[2] / (float)(BB * NPART);
        float kl  = -0.5f * sums[3] / (float)BB;
        float total = 1.0f * cd + 0.01f * kl + 0.5f * fid;
        out[0] = total;
        out[1] = cd;
        out[2] = kl;
        out[3] = fid;
    }
}

// ---------------------------------------------------------------------------
extern "C" void kernel_launch(void* const* d_in, const int* in_sizes, int n_in,
                              void* d_out, int out_size) {
    const float* pred    = (const float*)d_in[0];
    const float* full    = (const float*)d_in[1];
    const float* partial = (const float*)d_in[2];
    const float* mu      = (const float*)d_in[3];
    const float* logvar  = (const float*)d_in[4];
    float* out = (float*)d_out;

    float *pf, *fp, *pp, *pt;
    cudaGetSymbolAddress((void**)&pf, g_pf);
    cudaGetSymbolAddress((void**)&fp, g_fp);
    cudaGetSymbolAddress((void**)&pp, g_part);
    cudaGetSymbolAddress((void**)&pt, g_partial);

    cudaMemsetAsync(pf, 0x7f, BB * NFULL * sizeof(float));
    cudaMemsetAsync(fp, 0x7f, BB * NFULL * sizeof(float));
    cudaMemsetAsync(pp, 0x7f, BB * NPART * sizeof(float));

    fused_rowmin_kernel<<<GRID, THREADS>>>(pred, full, partial, pf, fp, pp);

    reduce1_kernel<<<RBLKS, 256>>>(pf, fp, pp, mu, logvar, pt);
    reduce2_kernel<<<1, 128>>>(pt, out);
}